// round 15
// baseline (speedup 1.0000x reference)
#include <cuda_runtime.h>
#include <cstdint>
#include <cstddef>

#define B_ 256
#define S_ 512
#define T_ 128
#define HP 68   // half-block stride in floats: 64 + 4 pad -> disjoint banks

typedef unsigned long long ull;

__device__ float g_acc;        // zero-init; reset by last CTA each run
__device__ unsigned g_done;    // zero-init; reset by last CTA each run

// Packed fp32x2 ops (sm_103a).
#define FMA2(d, a, b, c) asm("fma.rn.f32x2 %0, %1, %2, %3;" : "=l"(d) : "l"(a), "l"(b), "l"(c))
#define ADD2(d, a, b)    asm("add.rn.f32x2 %0, %1, %2;"     : "=l"(d) : "l"(a), "l"(b))
#define PACK2(d, lo, hi) asm("mov.b64 %0, {%1, %2};"        : "=l"(d) : "f"(lo), "f"(hi))
#define UNPK2(lo, hi, s) asm("mov.b64 {%0, %1}, %2;"        : "=f"(lo), "=f"(hi) : "l"(s))

// ---------------------------------------------------------------------------
// Fully fused CRF. 1 batch per CTA (grid 256), 256 threads, 2 CTAs/SM (regs
// capped at 128 by launch_bounds -> Mc[32]=64 regs fits without spill, unlike
// the full-column variants which silently pinned at 255 regs / occ 1).
// Thread (j = tid>>1, h = tid&1) computes the half-dot over rows [64h,64h+64).
// Alpha is stored as two half-blocks with stride HP=68 floats (272B): within a
// warp, even lanes (h=0) and odd lanes (h=1) read two addresses on DISJOINT
// bank sets -> every LDS.128 is a single wavefront (fixes R9's 2-way conflict).
// Halves combine with one shfl_xor(1) (commutative add -> bit-identical in
// both lanes) -> ONE barrier per step. Rescale by alpha_prev[0] every 4th step
// (worst-case growth ~e^64 << fp32 overflow e^88); scale is CTA-uniform so the
// recursion is algebraically exact regardless of its value.
// ---------------------------------------------------------------------------
__global__ void __launch_bounds__(256, 2) crf_fused(
    const float* __restrict__ em, const float* __restrict__ tr,
    const void* __restrict__ tags, const unsigned char* __restrict__ mask,
    float* __restrict__ out) {

    __shared__ __align__(16) float s_a[2][2][HP];   // [buf][half][64+pad]
    __shared__ float s_red[8];
    __shared__ int   s_flags[2];

    const int tid  = threadIdx.x;
    const int lane = tid & 31;
    const int w    = tid >> 5;
    const int j    = tid >> 1;       // output column 0..127
    const int h    = tid & 1;        // row half: rows [64h, 64h+64)
    const size_t b = blockIdx.x;

    // ---- dtype probe (JAX x64-off downcasts int64 tags to int32) ----------
    // tags < 128 => int64 buffer has all odd int32 words zero; P(fp) ~128^-64.
    if (tid == 0) {
        const int* t32 = (const int*)tags;
        int all0 = 1;
        #pragma unroll
        for (int i = 0; i < 64; ++i)
            if (t32[2 * i + 1] != 0) all0 = 0;
        s_flags[0] = all0;
        const unsigned char* mk = mask;
        s_flags[1] = (mk[0] != 0 && mk[1] == 0 && mk[2] == 0 && mk[3] == 0) ? 4 : 1;
    }
    __syncthreads();
    const int t64 = s_flags[0], mst = s_flags[1];

    // ---- gold score for this batch (negated into g_acc) --------------------
    {
        const long long* tg64 = (const long long*)tags + b * S_;
        const int*       tg32 = (const int*)tags + b * S_;
        const unsigned char* mk = mask + b * S_ * mst;
        float sum = 0.0f;
        for (int t = tid; t < S_; t += 256) {
            int tag = t64 ? (int)tg64[t] : tg32[t];
            float m = mk[(size_t)t * mst] ? 1.0f : 0.0f;
            sum += em[(b * S_ + t) * T_ + tag] * m;
            if (t + 1 < S_) {
                int tag2 = t64 ? (int)tg64[t + 1] : tg32[t + 1];
                float m2 = mk[(size_t)(t + 1) * mst] ? 1.0f : 0.0f;
                sum += tr[tag * T_ + tag2] * m2;
            }
        }
        for (int off = 16; off; off >>= 1)
            sum += __shfl_xor_sync(0xffffffffu, sum, off);
        if (lane == 0) s_red[w] = sum;
        __syncthreads();
        if (tid == 0) {
            float s = 0.0f;
            #pragma unroll
            for (int k = 0; k < 8; ++k) s += s_red[k];
            atomicAdd(&g_acc, -s);
        }
        __syncthreads();   // s_red reused at the end
    }

    // ---- Mc: rows [64h, 64h+64) of column j, 32 packed pairs (64 regs) -----
    ull Mc[32];
    {
        const int r0 = 64 * h;
        #pragma unroll
        for (int k = 0; k < 32; ++k) {
            float m0 = expf(tr[(r0 + 2 * k) * T_ + j]);
            float m1 = expf(tr[(r0 + 2 * k + 1) * T_ + j]);
            PACK2(Mc[k], m0, m1);
        }
    }

    // ---- init: alpha_0 = exp(e0), logacc = 0 -------------------------------
    float e0 = em[(b * S_ + 0) * T_ + j];
    if (h == 0) s_a[0][j >> 6][j & 63] = __expf(e0);
    float logacc = 0.0f;              // uniform across CTA

    // emission prefetch ring (3 deep); lane pairs read same addr (broadcast)
    float ec = em[(b * S_ + 1) * T_ + j];
    float en = em[(b * S_ + 2) * T_ + j];
    float ef = em[(b * S_ + 3) * T_ + j];
    __syncthreads();

    // ---- main recursion: ONE barrier per step ------------------------------
    float v = 0.0f;
    #pragma unroll 1
    for (int t = 1; t < S_; ++t) {
        const int rb = (t - 1) & 1, wb = t & 1;

        // periodic CTA-uniform rescale from previous alpha[0] (broadcast LDS)
        float sc = 1.0f;
        if ((t & 3) == 1) {
            float c = s_a[rb][0][0];
            sc = __fdividef(1.0f, c);
            logacc += __logf(c);
        }

        // fire next prefetch LDG early so DRAM latency hides under FMA block
        int t3 = (t + 3 < S_) ? t + 3 : S_ - 1;
        float eg = em[(b * S_ + t3) * T_ + j];

        float ex = __expf(ec);

        // half-dot: 16 LDS.128 (1 wavefront each: 2 addrs, disjoint banks)
        // + 32 FMA2 in 4 chains (depth 8)
        const ulonglong2* A = (const ulonglong2*)s_a[rb][h];
        ull a0 = 0ull, a1 = 0ull, a2 = 0ull, a3 = 0ull;
        #pragma unroll
        for (int k = 0; k < 16; k += 2) {
            ulonglong2 x0 = A[k];
            ulonglong2 x1 = A[k + 1];
            FMA2(a0, x0.x, Mc[2 * k],     a0);
            FMA2(a1, x0.y, Mc[2 * k + 1], a1);
            FMA2(a2, x1.x, Mc[2 * k + 2], a2);
            FMA2(a3, x1.y, Mc[2 * k + 3], a3);
        }
        ADD2(a0, a0, a1); ADD2(a2, a2, a3); ADD2(a0, a0, a2);
        float lo, hi;
        UNPK2(lo, hi, a0);
        float p = lo + hi;
        p += __shfl_xor_sync(0xffffffffu, p, 1);   // combine halves (exact)
        v = p * sc * ex;

        if (h == 0) s_a[wb][j >> 6][j & 63] = v;

        // rotate ring
        ec = en; en = ef; ef = eg;
        __syncthreads();
    }

    // ---- finish: partition_b = log(sum_j v) + logacc (h=0 lanes) -----------
    float s = (h == 0) ? v : 0.0f;
    for (int off = 16; off; off >>= 1)
        s += __shfl_xor_sync(0xffffffffu, s, off);
    if (lane == 0) s_red[w] = s;
    __syncthreads();
    if (tid == 0) {
        float tot = 0.0f;
        #pragma unroll
        for (int k = 0; k < 8; ++k) tot += s_red[k];
        atomicAdd(&g_acc, logf(tot) + logacc);
        __threadfence();
        unsigned r = atomicAdd(&g_done, 1u);
        if (r == B_ - 1) {                 // last CTA: publish + reset
            float res = atomicExch(&g_acc, 0.0f);
            out[0] = res;
            atomicExch(&g_done, 0u);
        }
    }
}

extern "C" void kernel_launch(void* const* d_in, const int* in_sizes, int n_in,
                              void* d_out, int out_size) {
    const float* em         = (const float*)d_in[0];
    const void* tags        = d_in[1];
    const unsigned char* mk = (const unsigned char*)d_in[2];
    const float* tr         = (const float*)d_in[3];

    crf_fused<<<B_, 256>>>(em, tr, tags, mk, (float*)d_out);
}

// round 16
// speedup vs baseline: 1.6124x; 1.6124x over previous
#include <cuda_runtime.h>
#include <cuda_bf16.h>
#include <cstdint>
#include <cstring>
#include <cstddef>

#define B_ 256
#define S_ 512
#define T_ 128

typedef __nv_bfloat162 bf2;

__device__ float g_acc;        // zero-init; reset by last CTA each run
__device__ unsigned g_done;    // zero-init; reset by last CTA each run

static __device__ __forceinline__ bf2 asbf2(unsigned u) {
    bf2 r; memcpy(&r, &u, 4); return r;
}

// ---------------------------------------------------------------------------
// Fully fused CRF, bf16 inner product. 1 batch per CTA (grid 256), 128 threads
// (thread = output column j), occupancy 2 (regs ~115 << 255: Mc is 64 bf16x2 =
// 64 regs instead of 128 fp32 regs -> ptxas finally has scheduling headroom).
// alpha is stored in smem as bf16 (64 u32 words of packed row-pairs): each
// warp-uniform broadcast LDS.128 feeds 8 alpha values / 4 HFMA2 -> 16 LDS per
// warp per step (half of the fp32 variant). HFMA2 is full-rate (rt2), so the
// MAC floor is unchanged while issue + register pressure drop.
// Numerics: rescale (every 4th step) uses the QUANTIZED alpha[0] read back
// from smem, so the rescaled recursion stays algebraically exact; bf16
// round-to-nearest noise (~0.2%) aggregates to ~1e-5 relative on the result.
// One __syncthreads per step.
// ---------------------------------------------------------------------------
__global__ void __launch_bounds__(128, 2) crf_fused(
    const float* __restrict__ em, const float* __restrict__ tr,
    const void* __restrict__ tags, const unsigned char* __restrict__ mask,
    float* __restrict__ out) {

    __shared__ __align__(16) unsigned s_a[2][64];   // [buf][row-pair] bf16x2
    __shared__ float s_red[4];
    __shared__ int   s_flags[2];

    const int j    = threadIdx.x;    // 0..127 : output column
    const int w    = j >> 5;
    const int lane = j & 31;
    const size_t b = blockIdx.x;

    // ---- dtype probe (JAX x64-off downcasts int64 tags to int32) ----------
    // tags < 128 => int64 buffer has all odd int32 words zero; P(fp) ~128^-64.
    if (j == 0) {
        const int* t32 = (const int*)tags;
        int all0 = 1;
        #pragma unroll
        for (int i = 0; i < 64; ++i)
            if (t32[2 * i + 1] != 0) all0 = 0;
        s_flags[0] = all0;
        const unsigned char* mk = mask;
        s_flags[1] = (mk[0] != 0 && mk[1] == 0 && mk[2] == 0 && mk[3] == 0) ? 4 : 1;
    }
    __syncthreads();
    const int t64 = s_flags[0], mst = s_flags[1];

    // ---- gold score for this batch (negated into g_acc), full fp32 ---------
    {
        const long long* tg64 = (const long long*)tags + b * S_;
        const int*       tg32 = (const int*)tags + b * S_;
        const unsigned char* mk = mask + b * S_ * mst;
        float sum = 0.0f;
        for (int t = j; t < S_; t += 128) {
            int tag = t64 ? (int)tg64[t] : tg32[t];
            float m = mk[(size_t)t * mst] ? 1.0f : 0.0f;
            sum += em[(b * S_ + t) * T_ + tag] * m;
            if (t + 1 < S_) {
                int tag2 = t64 ? (int)tg64[t + 1] : tg32[t + 1];
                float m2 = mk[(size_t)(t + 1) * mst] ? 1.0f : 0.0f;
                sum += tr[tag * T_ + tag2] * m2;
            }
        }
        for (int off = 16; off; off >>= 1)
            sum += __shfl_xor_sync(0xffffffffu, sum, off);
        if (lane == 0) s_red[w] = sum;
        __syncthreads();
        if (j == 0)
            atomicAdd(&g_acc, -(s_red[0] + s_red[1] + s_red[2] + s_red[3]));
        __syncthreads();   // s_red reused at the end
    }

    // ---- Mc column j as bf16 pairs: Mc[p] = (expT[2p][j], expT[2p+1][j]) ---
    bf2 Mc[64];
    #pragma unroll
    for (int p = 0; p < 64; ++p) {
        bf2 m;
        m.x = __float2bfloat16_rn(expf(tr[(2 * p) * T_ + j]));
        m.y = __float2bfloat16_rn(expf(tr[(2 * p + 1) * T_ + j]));
        Mc[p] = m;
    }

    // ---- init: alpha_0 = exp(e0) (bf16 in smem), logacc = 0 ----------------
    float e0 = em[(b * S_ + 0) * T_ + j];
    ((unsigned short*)s_a[0])[j] =
        __bfloat16_as_ushort(__float2bfloat16_rn(__expf(e0)));
    float logacc = 0.0f;              // uniform across CTA

    // emission prefetch ring (3 deep)
    float ec = em[(b * S_ + 1) * T_ + j];
    float en = em[(b * S_ + 2) * T_ + j];
    float ef = em[(b * S_ + 3) * T_ + j];
    __syncthreads();

    // ---- main recursion: one barrier/step, rescale every 4th step ----------
    float v = 0.0f;
    #pragma unroll 1
    for (int t = 1; t < S_; ++t) {
        const int rb = (t - 1) & 1, wb = t & 1;

        // periodic CTA-uniform rescale from quantized alpha_prev[0] (broadcast)
        float sc = 1.0f;
        if ((t & 3) == 1) {
            unsigned w0 = s_a[rb][0];
            float c = __bfloat162float(__ushort_as_bfloat16((unsigned short)(w0 & 0xffffu)));
            sc = __fdividef(1.0f, c);
            logacc += __logf(c);
        }

        // fire next prefetch LDG early so DRAM latency hides under FMA block
        int t3 = (t + 3 < S_) ? t + 3 : S_ - 1;
        float eg = em[(b * S_ + t3) * T_ + j];

        float ex = __expf(ec);

        // 128-term bf16 dot: 16 broadcast LDS.128 (8 alpha each) + 64 HFMA2
        // in 8 independent chains (depth 16)
        const uint4* A = (const uint4*)s_a[rb];
        bf2 z; z.x = __ushort_as_bfloat16(0); z.y = __ushort_as_bfloat16(0);
        bf2 a0 = z, a1 = z, a2 = z, a3 = z, a4 = z, a5 = z, a6 = z, a7 = z;
        #pragma unroll
        for (int k = 0; k < 16; k += 2) {
            uint4 x0 = A[k];
            uint4 x1 = A[k + 1];
            a0 = __hfma2(asbf2(x0.x), Mc[4 * k + 0], a0);
            a1 = __hfma2(asbf2(x0.y), Mc[4 * k + 1], a1);
            a2 = __hfma2(asbf2(x0.z), Mc[4 * k + 2], a2);
            a3 = __hfma2(asbf2(x0.w), Mc[4 * k + 3], a3);
            a4 = __hfma2(asbf2(x1.x), Mc[4 * k + 4], a4);
            a5 = __hfma2(asbf2(x1.y), Mc[4 * k + 5], a5);
            a6 = __hfma2(asbf2(x1.z), Mc[4 * k + 6], a6);
            a7 = __hfma2(asbf2(x1.w), Mc[4 * k + 7], a7);
        }
        a0 = __hadd2(a0, a1); a2 = __hadd2(a2, a3);
        a4 = __hadd2(a4, a5); a6 = __hadd2(a6, a7);
        a0 = __hadd2(a0, a2); a4 = __hadd2(a4, a6);
        a0 = __hadd2(a0, a4);
        float2 fd = __bfloat1622float2(a0);
        float dot = fd.x + fd.y;

        v = dot * sc * ex;                       // fp32 value of alpha_t[j]
        ((unsigned short*)s_a[wb])[j] =
            __bfloat16_as_ushort(__float2bfloat16_rn(v));

        // rotate ring
        ec = en; en = ef; ef = eg;
        __syncthreads();
    }

    // ---- finish: partition_b = log(sum_j v) + logacc (fp32 v) --------------
    float s = v;
    for (int off = 16; off; off >>= 1)
        s += __shfl_xor_sync(0xffffffffu, s, off);
    if (lane == 0) s_red[w] = s;
    __syncthreads();
    if (j == 0) {
        float tot = s_red[0] + s_red[1] + s_red[2] + s_red[3];
        atomicAdd(&g_acc, logf(tot) + logacc);
        __threadfence();
        unsigned r = atomicAdd(&g_done, 1u);
        if (r == B_ - 1) {                 // last CTA: publish + reset
            float res = atomicExch(&g_acc, 0.0f);
            out[0] = res;
            atomicExch(&g_done, 0u);
        }
    }
}

extern "C" void kernel_launch(void* const* d_in, const int* in_sizes, int n_in,
                              void* d_out, int out_size) {
    const float* em         = (const float*)d_in[0];
    const void* tags        = d_in[1];
    const unsigned char* mk = (const unsigned char*)d_in[2];
    const float* tr         = (const float*)d_in[3];

    crf_fused<<<B_, 128>>>(em, tr, tags, mk, (float*)d_out);
}